// round 5
// baseline (speedup 1.0000x reference)
#include <cuda_runtime.h>
#include <math.h>

#define HH 64
#define WW 64
#define BB 2
#define CC 128
#define NH 4
#define DH 32
#define KS 7
#define KK 49
#define NTOK (BB*HH*WW)   // 8192
#define QKV_STRIDE (3*CC) // 384

typedef unsigned long long ull;

// packed f32x2 helpers (Blackwell sm_100+)
__device__ __forceinline__ ull ffma2(ull a, ull b, ull c) {
    ull d;
    asm("fma.rn.f32x2 %0, %1, %2, %3;" : "=l"(d) : "l"(a), "l"(b), "l"(c));
    return d;
}
__device__ __forceinline__ ull pack2(float x, float y) {
    ull r; asm("mov.b64 %0, {%1, %2};" : "=l"(r) : "f"(x), "f"(y)); return r;
}
__device__ __forceinline__ float2 unpack2(ull v) {
    float2 r; asm("mov.b64 {%0, %1}, %2;" : "=f"(r.x), "=f"(r.y) : "l"(v)); return r;
}

// scratch (device globals: no allocation allowed)
__device__ float g_qkv[NTOK * 3 * CC];
__device__ float g_att[NTOK * CC];
__device__ float g_y1 [NTOK * CC];
__device__ float g_y2 [NTOK * CC];

// ----------------------------------------------------------------------------
// SGEMM v4: BM=BN=64, BK=32, 256 thr, 4x4 microtile, FFMA2 inner loop.
// ----------------------------------------------------------------------------
#define BK 32
#define SPITCH 68   // 64+4 floats, 16B-aligned rows, stride 4 banks

__global__ void __launch_bounds__(256) sgemm4_kernel(
    const float* __restrict__ A, int a_nchw,
    const float* __restrict__ W,
    const float* __restrict__ bias,
    float* __restrict__ Cout, int N)
{
    __shared__ float sA[BK][SPITCH];   // [k][m]
    __shared__ float sB[BK][SPITCH];   // [k][n]

    const int bm = blockIdx.x * 64;
    const int bn = blockIdx.y * 64;
    const int tid = threadIdx.x;
    const int tx = tid & 15;
    const int ty = tid >> 4;

    ull acc[4][2];
    #pragma unroll
    for (int i = 0; i < 4; i++) { acc[i][0] = 0ull; acc[i][1] = 0ull; }

    for (int k0 = 0; k0 < CC; k0 += BK) {
        // ---- A tile ----
        if (a_nchw) {
            const int b = bm >> 12;
            const int sp4 = (bm & 4095) >> 2;
            #pragma unroll
            for (int r = 0; r < 2; r++) {
                int idx = tid + r*256;
                int k = idx >> 4, m4 = idx & 15;
                float4 v = ((const float4*)A)[(b*CC + k0 + k)*1024 + sp4 + m4];
                *(float4*)&sA[k][m4*4] = v;
            }
        } else {
            #pragma unroll
            for (int r = 0; r < 2; r++) {
                int idx = tid + r*256;
                int m = idx >> 3, k4 = idx & 7;
                float4 v = ((const float4*)A)[(bm + m)*32 + (k0 >> 2) + k4];
                sA[k4*4+0][m] = v.x; sA[k4*4+1][m] = v.y;
                sA[k4*4+2][m] = v.z; sA[k4*4+3][m] = v.w;
            }
        }
        // ---- W tile ----
        #pragma unroll
        for (int r = 0; r < 2; r++) {
            int idx = tid + r*256;
            int n = idx >> 3, k4 = idx & 7;
            float4 v = ((const float4*)W)[(bn + n)*32 + (k0 >> 2) + k4];
            sB[k4*4+0][n] = v.x; sB[k4*4+1][n] = v.y;
            sB[k4*4+2][n] = v.z; sB[k4*4+3][n] = v.w;
        }
        __syncthreads();

        #pragma unroll
        for (int k = 0; k < BK; k++) {
            float4 a = *(const float4*)&sA[k][ty*4];
            ulonglong2 b2 = *(const ulonglong2*)&sB[k][tx*4]; // (b0,b1),(b2,b3)
            ull ad[4];
            ad[0] = pack2(a.x, a.x); ad[1] = pack2(a.y, a.y);
            ad[2] = pack2(a.z, a.z); ad[3] = pack2(a.w, a.w);
            #pragma unroll
            for (int i = 0; i < 4; i++) {
                acc[i][0] = ffma2(ad[i], b2.x, acc[i][0]);
                acc[i][1] = ffma2(ad[i], b2.y, acc[i][1]);
            }
        }
        __syncthreads();
    }

    float4 bb = *(const float4*)&bias[bn + tx*4];
    #pragma unroll
    for (int i = 0; i < 4; i++) {
        float2 u0 = unpack2(acc[i][0]);
        float2 u1 = unpack2(acc[i][1]);
        float4 o;
        o.x = u0.x + bb.x; o.y = u0.y + bb.y;
        o.z = u1.x + bb.z; o.w = u1.y + bb.w;
        *(float4*)&Cout[(bm + ty*4 + i)*N + bn + tx*4] = o;
    }
}

// ----------------------------------------------------------------------------
// Attention v5: 2x2 pixel tile, 128 thr, warp = head.
// Score-by-window-token: lane = window token (2 rounds), k-row (all 32
// channels!) in regs, reused across 4 pixels' q via broadcast LDS.
// ----------------------------------------------------------------------------
#define KP 132
#define PP 68    // prob row pitch (floats)
#define ATTN_SMEM ((64*KP*2 + 4*KP + 16*PP) * 4)   // 74048 bytes

__global__ void __launch_bounds__(128) attn5_kernel(
    const float* __restrict__ qkv,
    const float* __restrict__ rpb,   // [NH][13][13]
    float* __restrict__ out)
{
    extern __shared__ float dsm[];
    float* sK = dsm;              // [64][KP]
    float* sV = sK + 64*KP;       // [64][KP]
    float* sq = sV + 64*KP;       // [4][KP]
    float* sp = sq + 4*KP;        // [16][PP]  probs

    const int blk = blockIdx.x;          // 2048
    const int b  = blk >> 10;
    const int ti = (blk >> 5) & 31;
    const int tj = blk & 31;
    const int i0 = ti*2, j0 = tj*2;
    const int r0 = min(max(i0 - 3, 0), HH - 8);
    const int c0 = min(max(j0 - 3, 0), WW - 8);
    const int tid = threadIdx.x;
    const int h = tid >> 5;
    const int lane = tid & 31;

    // ---- stage K,V (8x8 window) + scaled q ----
    #pragma unroll
    for (int it = 0; it < 32; it++) {
        int idx = tid + it*128;
        int row = idx >> 6, c4 = idx & 63;
        int wr = row >> 3, wc = row & 7;
        int tt = (b*HH + r0 + wr)*WW + c0 + wc;
        float4 v = ((const float4*)qkv)[tt*96 + 32 + c4];
        if (c4 < 32) *(float4*)&sK[row*KP + c4*4] = v;
        else         *(float4*)&sV[row*KP + (c4-32)*4] = v;
    }
    {
        int p = tid >> 5, c4 = tid & 31;
        int tt = (b*HH + i0 + (p >> 1))*WW + j0 + (p & 1);
        float4 v = ((const float4*)qkv)[tt*96 + c4];
        const float s = 0.17677669529663687f;   // 32^-0.5
        v.x *= s; v.y *= s; v.z *= s; v.w *= s;
        *(float4*)&sq[p*KP + c4*4] = v;
    }
    __syncthreads();

    // per-pixel geometry
    int pwro[4], pwco[4], pbio[4], pbjo[4];
    #pragma unroll
    for (int p = 0; p < 4; p++) {
        int i = i0 + (p >> 1), j = j0 + (p & 1);
        int si = min(max(i - 3, 0), HH - KS);
        int sj = min(max(j - 3, 0), WW - KS);
        pwro[p] = si - r0;
        pwco[p] = sj - c0;
        pbio[p] = 6 - (i - si);
        pbjo[p] = 6 - (j - sj);
    }
    const float* rp = rpb + h*169;

    // ---- QK: lane = window token w (2 rounds); full 32-ch k-row in regs ----
    float sv[2][4];
    #pragma unroll
    for (int round = 0; round < 2; round++) {
        const int w = lane + 32*round;
        const int wr = w >> 3, wc = w & 7;
        ulonglong2 kreg[8];   // 8 x (2 f32x2) = 32 floats  (FULL head dim)
        const ulonglong2* kp = (const ulonglong2*)(sK + w*KP + h*DH);
        #pragma unroll
        for (int u = 0; u < 8; u++) kreg[u] = kp[u];

        #pragma unroll
        for (int p = 0; p < 4; p++) {
            const int np = wr - pwro[p];
            const int nq = wc - pwco[p];
            const bool valid = (np >= 0) & (np < KS) & (nq >= 0) & (nq < KS);
            ull a01 = 0ull, a23 = 0ull;
            const ulonglong2* qp = (const ulonglong2*)(sq + p*KP + h*DH);
            #pragma unroll
            for (int u = 0; u < 8; u++) {
                ulonglong2 q2 = qp[u];   // broadcast LDS.128
                a01 = ffma2(q2.x, kreg[u].x, a01);
                a23 = ffma2(q2.y, kreg[u].y, a23);
            }
            float2 f01 = unpack2(a01), f23 = unpack2(a23);
            float s = (f01.x + f01.y) + (f23.x + f23.y);
            if (valid)
                s += rp[(np + pbio[p])*13 + nq + pbjo[p]];
            sv[round][p] = valid ? s : -1e30f;
        }
    }

    // ---- softmax per pixel over 64 window tokens ----
    #pragma unroll
    for (int p = 0; p < 4; p++) {
        float m = fmaxf(sv[0][p], sv[1][p]);
        #pragma unroll
        for (int o = 16; o > 0; o >>= 1)
            m = fmaxf(m, __shfl_xor_sync(0xffffffffu, m, o));
        float e0 = __expf(sv[0][p] - m);
        float e1 = __expf(sv[1][p] - m);
        float sum = e0 + e1;
        #pragma unroll
        for (int o = 16; o > 0; o >>= 1)
            sum += __shfl_xor_sync(0xffffffffu, sum, o);
        float inv = 1.f / sum;
        sp[(h*4 + p)*PP + lane]      = e0 * inv;
        sp[(h*4 + p)*PP + 32 + lane] = e1 * inv;
    }
    __syncwarp();

    // ---- AV: lane = d; probs via float4 broadcast, skip zero quads ----
    #pragma unroll
    for (int p = 0; p < 4; p++) {
        const float* pr = sp + (h*4 + p)*PP;
        const float* vb = sV + h*DH + lane;
        float o = 0.f;
        #pragma unroll
        for (int u = 0; u < 16; u++) {
            float4 pw = ((const float4*)pr)[u];   // broadcast
            if (pw.x == 0.f && pw.y == 0.f && pw.z == 0.f && pw.w == 0.f)
                continue;
            const float* v4 = vb + (u*4)*KP;
            o += pw.x * v4[0*KP] + pw.y * v4[1*KP]
               + pw.z * v4[2*KP] + pw.w * v4[3*KP];
        }
        int i = i0 + (p >> 1), j = j0 + (p & 1);
        int tt = (b*HH + i)*WW + j;
        out[(size_t)tt*CC + h*DH + lane] = o;
    }
}

// ----------------------------------------------------------------------------
// Final LayerNorm over C + NHWC -> NCHW transpose.
// ----------------------------------------------------------------------------
__global__ void ln_kernel(const float* __restrict__ y,
                          const float* __restrict__ g,
                          const float* __restrict__ bta,
                          float* __restrict__ out)
{
    __shared__ float s[64][133];
    __shared__ float mu[64], rs[64];

    const int row = blockIdx.x;
    const int b = row >> 6, i = row & 63;
    const int base = row * 64 * CC;
    const int tid = threadIdx.x;

    for (int idx = tid; idx < 64*CC; idx += 256) {
        int jj = idx >> 7, c = idx & 127;
        s[jj][c] = y[base + idx];
    }
    __syncthreads();

    if (tid < 64) {
        float sum = 0.f, sq = 0.f;
        #pragma unroll 8
        for (int c = 0; c < CC; c++) {
            float v = s[tid][c];
            sum += v; sq += v*v;
        }
        float m = sum * (1.f/CC);
        mu[tid] = m;
        rs[tid] = rsqrtf(sq * (1.f/CC) - m*m + 1e-5f);
    }
    __syncthreads();

    for (int idx = tid; idx < 64*CC; idx += 256) {
        int c = idx >> 6, jj = idx & 63;
        float v = (s[jj][c] - mu[jj]) * rs[jj] * g[c] + bta[c];
        out[((b*CC + c)*HH + i)*WW + jj] = v;
    }
}

// ----------------------------------------------------------------------------
extern "C" void kernel_launch(void* const* d_in, const int* in_sizes, int n_in,
                              void* d_out, int out_size)
{
    const float* x      = (const float*)d_in[0];
    const float* qkv_w  = (const float*)d_in[1];
    const float* qkv_b  = (const float*)d_in[2];
    const float* rpb    = (const float*)d_in[3];
    const float* proj_w = (const float*)d_in[4];
    const float* proj_b = (const float*)d_in[5];
    const float* ln_g   = (const float*)d_in[6];
    const float* ln_b   = (const float*)d_in[7];
    float* outp = (float*)d_out;

    float *qkvbuf, *attbuf, *y1, *y2;
    cudaGetSymbolAddress((void**)&qkvbuf, g_qkv);
    cudaGetSymbolAddress((void**)&attbuf, g_att);
    cudaGetSymbolAddress((void**)&y1, g_y1);
    cudaGetSymbolAddress((void**)&y2, g_y2);

    static int smem_set = 0;
    if (!smem_set) {
        cudaFuncSetAttribute(attn5_kernel,
                             cudaFuncAttributeMaxDynamicSharedMemorySize,
                             ATTN_SMEM);
        smem_set = 1;
    }

    dim3 gq(NTOK/64, (3*CC)/64);   // 128 x 6
    dim3 gp(NTOK/64, CC/64);       // 128 x 2
    const int RPB_L = NH*13*13;
    const int NATB = BB*32*32;     // 2048

    // ---- layer 0 ----
    sgemm4_kernel<<<gq, 256>>>(x, 1, qkv_w, qkv_b, qkvbuf, 3*CC);
    attn5_kernel<<<NATB, 128, ATTN_SMEM>>>(qkvbuf, rpb, attbuf);
    sgemm4_kernel<<<gp, 256>>>(attbuf, 0, proj_w, proj_b, y1, CC);

    // ---- layer 1 ----
    sgemm4_kernel<<<gq, 256>>>(y1, 0, qkv_w + 3*CC*CC, qkv_b + 3*CC, qkvbuf, 3*CC);
    attn5_kernel<<<NATB, 128, ATTN_SMEM>>>(qkvbuf, rpb + RPB_L, attbuf);
    sgemm4_kernel<<<gp, 256>>>(attbuf, 0, proj_w + CC*CC, proj_b + CC, y2, CC);

    // ---- LN + transpose ----
    ln_kernel<<<BB*HH, 256>>>(y2, ln_g, ln_b, outp);
}

// round 6
// speedup vs baseline: 1.2546x; 1.2546x over previous
#include <cuda_runtime.h>
#include <math.h>

#define HH 64
#define WW 64
#define BB 2
#define CC 128
#define NH 4
#define DH 32
#define KS 7
#define KK 49
#define NTOK (BB*HH*WW)   // 8192
#define QKV_STRIDE (3*CC) // 384

// scratch (device globals: no allocation allowed)
__device__ float g_qkv[NTOK * 3 * CC];
__device__ float g_att[NTOK * CC];
__device__ float g_y1 [NTOK * CC];
__device__ float g_y2 [NTOK * CC];

// ----------------------------------------------------------------------------
// SGEMM v5: BM=BN=64, FULL-K staging (K=128 entirely in smem, one sync),
// 256 thr, 4x4 microtile, float4 shared loads.
// Dynamic smem: sA[128][68] + sB[128][68] = 69632 B.
// ----------------------------------------------------------------------------
#define SP 68   // pitch: 64+4 floats, 16B-aligned rows, stride 4 banks
#define GEMM_SMEM (2*CC*SP*4)

__global__ void __launch_bounds__(256) sgemm5_kernel(
    const float* __restrict__ A, int a_nchw,
    const float* __restrict__ W,
    const float* __restrict__ bias,
    float* __restrict__ Cout, int N)
{
    extern __shared__ float sm[];
    float* sA = sm;            // [k][m] pitch SP, k = 0..127
    float* sB = sm + CC*SP;    // [k][n] pitch SP

    const int bm = blockIdx.x * 64;
    const int bn = blockIdx.y * 64;
    const int tid = threadIdx.x;
    const int tx = tid & 15;
    const int ty = tid >> 4;

    // ---- stage ALL of A (64m x 128k) ----
    if (a_nchw) {
        // A[t][c] = X[b][c][sp]: global already [k][m]-contiguous
        const int b = bm >> 12;
        const int sp4 = (bm & 4095) >> 2;
        #pragma unroll
        for (int r = 0; r < 8; r++) {
            int idx = tid + r*256;          // 2048 float4s: 128k x 16m4
            int k = idx >> 4, m4 = idx & 15;
            float4 v = ((const float4*)A)[(b*CC + k)*1024 + sp4 + m4];
            *(float4*)&sA[k*SP + m4*4] = v;
        }
    } else {
        // token-major A[m][k]: transpose on store
        #pragma unroll
        for (int r = 0; r < 8; r++) {
            int idx = tid + r*256;          // 64m x 32k4
            int m = idx >> 5, k4 = idx & 31;
            float4 v = ((const float4*)A)[(bm + m)*32 + k4];
            sA[(k4*4+0)*SP + m] = v.x; sA[(k4*4+1)*SP + m] = v.y;
            sA[(k4*4+2)*SP + m] = v.z; sA[(k4*4+3)*SP + m] = v.w;
        }
    }
    // ---- stage ALL of W (64n x 128k), transpose on store ----
    #pragma unroll
    for (int r = 0; r < 8; r++) {
        int idx = tid + r*256;
        int n = idx >> 5, k4 = idx & 31;
        float4 v = ((const float4*)W)[(bn + n)*32 + k4];
        sB[(k4*4+0)*SP + n] = v.x; sB[(k4*4+1)*SP + n] = v.y;
        sB[(k4*4+2)*SP + n] = v.z; sB[(k4*4+3)*SP + n] = v.w;
    }
    __syncthreads();

    // ---- compute: 128 uninterrupted k-steps ----
    float acc[4][4] = {};
    const float* pa = sA + ty*4;
    const float* pb = sB + tx*4;
    #pragma unroll 8
    for (int k = 0; k < CC; k++) {
        float4 a = *(const float4*)(pa + k*SP);
        float4 b = *(const float4*)(pb + k*SP);
        float av[4] = {a.x,a.y,a.z,a.w};
        float bv[4] = {b.x,b.y,b.z,b.w};
        #pragma unroll
        for (int i = 0; i < 4; i++)
            #pragma unroll
            for (int j = 0; j < 4; j++)
                acc[i][j] += av[i] * bv[j];
    }

    float4 bb = *(const float4*)&bias[bn + tx*4];
    #pragma unroll
    for (int i = 0; i < 4; i++) {
        float4 o;
        o.x = acc[i][0] + bb.x; o.y = acc[i][1] + bb.y;
        o.z = acc[i][2] + bb.z; o.w = acc[i][3] + bb.w;
        *(float4*)&Cout[(bm + ty*4 + i)*N + bn + tx*4] = o;
    }
}

// ----------------------------------------------------------------------------
// Attention v3 (known good): 2x2 pixel tile, 128 thr, warp = head.
// 8x8 K+V window in smem.
// ----------------------------------------------------------------------------
#define KP 132
#define ATTN_SMEM ((64*KP*2 + 4*KP + 4*52) * 4)   // 70528 bytes

__global__ void __launch_bounds__(128) attn3_kernel(
    const float* __restrict__ qkv,
    const float* __restrict__ rpb,   // [NH][13][13]
    float* __restrict__ out)
{
    extern __shared__ float dsm[];
    float* sK = dsm;              // [64][KP]
    float* sV = sK + 64*KP;       // [64][KP]
    float* sq = sV + 64*KP;       // [4][KP]
    float* sc = sq + 4*KP;        // [4 heads][52]

    const int blk = blockIdx.x;          // 2048 = 2 * 32 * 32
    const int b  = blk >> 10;
    const int ti = (blk >> 5) & 31;
    const int tj = blk & 31;
    const int i0 = ti*2, j0 = tj*2;
    const int r0 = min(max(i0 - 3, 0), HH - 8);
    const int c0 = min(max(j0 - 3, 0), WW - 8);
    const int tid = threadIdx.x;
    const int h = tid >> 5;
    const int lane = tid & 31;

    // ---- load 8x8 window of K+V ----
    #pragma unroll
    for (int it = 0; it < 32; it++) {
        int idx = tid + it*128;
        int row = idx >> 6, c4 = idx & 63;
        int wr = row >> 3, wc = row & 7;
        int tt = (b*HH + r0 + wr)*WW + c0 + wc;
        float4 v = ((const float4*)qkv)[tt*96 + 32 + c4];
        if (c4 < 32) *(float4*)&sK[row*KP + c4*4] = v;
        else         *(float4*)&sV[row*KP + (c4-32)*4] = v;
    }
    // ---- load 4 q vectors, scaled ----
    {
        int p = tid >> 5, c4 = tid & 31;
        int tt = (b*HH + i0 + (p >> 1))*WW + j0 + (p & 1);
        float4 v = ((const float4*)qkv)[tt*96 + c4];
        const float s = 0.17677669529663687f;   // 32^-0.5
        v.x *= s; v.y *= s; v.z *= s; v.w *= s;
        *(float4*)&sq[p*KP + c4*4] = v;
    }
    __syncthreads();

    const float* rp = rpb + h*169;

    #pragma unroll
    for (int p = 0; p < 4; p++) {
        const int i = i0 + (p >> 1), j = j0 + (p & 1);
        const int si = min(max(i - 3, 0), HH - KS);
        const int sj = min(max(j - 3, 0), WW - KS);
        const int wr0 = si - r0, wc0 = sj - c0;
        const int bi0 = 6 - (i - si), bj0 = 6 - (j - sj);

        float4 q[8];
        const float4* qp = (const float4*)(sq + p*KP + h*DH);
        #pragma unroll
        for (int u = 0; u < 8; u++) q[u] = qp[u];

        float s0, s1;
        {
            int n = lane;
            int np = n/7, nq = n - np*7;
            const float4* kp = (const float4*)(sK + ((wr0+np)*8 + wc0+nq)*KP + h*DH);
            float ax=0.f, ay=0.f, az=0.f, aw=0.f;
            #pragma unroll
            for (int u = 0; u < 8; u++) {
                float4 kv = kp[u];
                ax += q[u].x*kv.x; ay += q[u].y*kv.y;
                az += q[u].z*kv.z; aw += q[u].w*kv.w;
            }
            s0 = (ax+ay) + (az+aw) + rp[(np+bi0)*13 + nq+bj0];
        }
        const int n2 = lane + 32;
        if (n2 < KK) {
            int np = n2/7, nq = n2 - np*7;
            const float4* kp = (const float4*)(sK + ((wr0+np)*8 + wc0+nq)*KP + h*DH);
            float ax=0.f, ay=0.f, az=0.f, aw=0.f;
            #pragma unroll
            for (int u = 0; u < 8; u++) {
                float4 kv = kp[u];
                ax += q[u].x*kv.x; ay += q[u].y*kv.y;
                az += q[u].z*kv.z; aw += q[u].w*kv.w;
            }
            s1 = (ax+ay) + (az+aw) + rp[(np+bi0)*13 + nq+bj0];
        } else s1 = -1e30f;

        // ---- softmax (warp-resident) ----
        float m = fmaxf(s0, s1);
        #pragma unroll
        for (int o = 16; o > 0; o >>= 1) m = fmaxf(m, __shfl_xor_sync(0xffffffffu, m, o));
        float e0 = __expf(s0 - m);
        float e1 = (n2 < KK) ? __expf(s1 - m) : 0.f;
        float sum = e0 + e1;
        #pragma unroll
        for (int o = 16; o > 0; o >>= 1) sum += __shfl_xor_sync(0xffffffffu, sum, o);
        const float inv = 1.f / sum;

        __syncwarp();
        sc[h*52 + lane] = e0 * inv;
        if (n2 < KK) sc[h*52 + n2] = e1 * inv;
        __syncwarp();

        // ---- AV: lane = d, probs via smem broadcast ----
        float oa = 0.f, ob = 0.f;
        #pragma unroll
        for (int np = 0; np < 7; np++) {
            const float* vrow = sV + ((wr0+np)*8 + wc0)*KP + h*DH + lane;
            const float* prow = sc + h*52 + np*7;
            oa += prow[0]*vrow[0*KP] + prow[2]*vrow[2*KP]
                + prow[4]*vrow[4*KP] + prow[6]*vrow[6*KP];
            ob += prow[1]*vrow[1*KP] + prow[3]*vrow[3*KP]
                + prow[5]*vrow[5*KP];
        }
        int tt = (b*HH + i)*WW + j;
        out[(size_t)tt*CC + h*DH + lane] = oa + ob;
        __syncwarp();
    }
}

// ----------------------------------------------------------------------------
// Final LayerNorm over C + NHWC -> NCHW transpose.
// ----------------------------------------------------------------------------
__global__ void ln_kernel(const float* __restrict__ y,
                          const float* __restrict__ g,
                          const float* __restrict__ bta,
                          float* __restrict__ out)
{
    __shared__ float s[64][133];
    __shared__ float mu[64], rs[64];

    const int row = blockIdx.x;
    const int b = row >> 6, i = row & 63;
    const int base = row * 64 * CC;
    const int tid = threadIdx.x;

    for (int idx = tid; idx < 64*CC; idx += 256) {
        int jj = idx >> 7, c = idx & 127;
        s[jj][c] = y[base + idx];
    }
    __syncthreads();

    if (tid < 64) {
        float sum = 0.f, sq = 0.f;
        #pragma unroll 8
        for (int c = 0; c < CC; c++) {
            float v = s[tid][c];
            sum += v; sq += v*v;
        }
        float m = sum * (1.f/CC);
        mu[tid] = m;
        rs[tid] = rsqrtf(sq * (1.f/CC) - m*m + 1e-5f);
    }
    __syncthreads();

    for (int idx = tid; idx < 64*CC; idx += 256) {
        int c = idx >> 6, jj = idx & 63;
        float v = (s[jj][c] - mu[jj]) * rs[jj] * g[c] + bta[c];
        out[((b*CC + c)*HH + i)*WW + jj] = v;
    }
}

// ----------------------------------------------------------------------------
extern "C" void kernel_launch(void* const* d_in, const int* in_sizes, int n_in,
                              void* d_out, int out_size)
{
    const float* x      = (const float*)d_in[0];
    const float* qkv_w  = (const float*)d_in[1];
    const float* qkv_b  = (const float*)d_in[2];
    const float* rpb    = (const float*)d_in[3];
    const float* proj_w = (const float*)d_in[4];
    const float* proj_b = (const float*)d_in[5];
    const float* ln_g   = (const float*)d_in[6];
    const float* ln_b   = (const float*)d_in[7];
    float* outp = (float*)d_out;

    float *qkvbuf, *attbuf, *y1, *y2;
    cudaGetSymbolAddress((void**)&qkvbuf, g_qkv);
    cudaGetSymbolAddress((void**)&attbuf, g_att);
    cudaGetSymbolAddress((void**)&y1, g_y1);
    cudaGetSymbolAddress((void**)&y2, g_y2);

    static int smem_set = 0;
    if (!smem_set) {
        cudaFuncSetAttribute(attn3_kernel,
                             cudaFuncAttributeMaxDynamicSharedMemorySize,
                             ATTN_SMEM);
        cudaFuncSetAttribute(sgemm5_kernel,
                             cudaFuncAttributeMaxDynamicSharedMemorySize,
                             GEMM_SMEM);
        smem_set = 1;
    }

    dim3 gq(NTOK/64, (3*CC)/64);   // 128 x 6
    dim3 gp(NTOK/64, CC/64);       // 128 x 2
    const int RPB_L = NH*13*13;
    const int NATB = BB*32*32;     // 2048

    // ---- layer 0 ----
    sgemm5_kernel<<<gq, 256, GEMM_SMEM>>>(x, 1, qkv_w, qkv_b, qkvbuf, 3*CC);
    attn3_kernel<<<NATB, 128, ATTN_SMEM>>>(qkvbuf, rpb, attbuf);
    sgemm5_kernel<<<gp, 256, GEMM_SMEM>>>(attbuf, 0, proj_w, proj_b, y1, CC);

    // ---- layer 1 ----
    sgemm5_kernel<<<gq, 256, GEMM_SMEM>>>(y1, 0, qkv_w + 3*CC*CC, qkv_b + 3*CC, qkvbuf, 3*CC);
    attn3_kernel<<<NATB, 128, ATTN_SMEM>>>(qkvbuf, rpb + RPB_L, attbuf);
    sgemm5_kernel<<<gp, 256, GEMM_SMEM>>>(attbuf, 0, proj_w + CC*CC, proj_b + CC, y2, CC);

    // ---- LN + transpose ----
    ln_kernel<<<BB*HH, 256>>>(y2, ln_g, ln_b, outp);
}

// round 7
// speedup vs baseline: 1.7079x; 1.3613x over previous
#include <cuda_runtime.h>
#include <math.h>

#define HH 64
#define WW 64
#define BB 2
#define CC 128
#define NH 4
#define DH 32
#define KS 7
#define KK 49
#define NTOK (BB*HH*WW)   // 8192
#define QKV_STRIDE (3*CC) // 384

// scratch (device globals: no allocation allowed)
__device__ float g_qkv[NTOK * 3 * CC];
__device__ float g_att[NTOK * CC];
__device__ float g_y1 [NTOK * CC];
__device__ float g_y2 [NTOK * CC];

// ----------------------------------------------------------------------------
// tf32 helpers
// ----------------------------------------------------------------------------
__device__ __forceinline__ unsigned f2tf32(float f) {
    unsigned u;
    asm("cvt.rna.tf32.f32 %0, %1;" : "=r"(u) : "f"(f));
    return u;
}
__device__ __forceinline__ void split_tf32(float f, unsigned& hi, unsigned& lo) {
    hi = f2tf32(f);
    lo = f2tf32(f - __uint_as_float(hi));
}
__device__ __forceinline__ void mma8(float* c, const unsigned* a, const unsigned* b) {
    asm volatile(
        "mma.sync.aligned.m16n8k8.row.col.f32.tf32.tf32.f32 "
        "{%0,%1,%2,%3}, {%4,%5,%6,%7}, {%8,%9}, {%0,%1,%2,%3};"
        : "+f"(c[0]), "+f"(c[1]), "+f"(c[2]), "+f"(c[3])
        : "r"(a[0]), "r"(a[1]), "r"(a[2]), "r"(a[3]),
          "r"(b[0]), "r"(b[1]));
}

// ----------------------------------------------------------------------------
// Tensor-core SGEMM (3xTF32): C[M,N] = A[M,128] @ W[N,128]^T + bias.
// BM=BN=64, BK=64 (2 k-tiles). 256 thr = 8 warps (2m x 4n), warp tile 32x16.
// ----------------------------------------------------------------------------
#define SPK 68   // smem pitch (floats)

__global__ void __launch_bounds__(256) sgemm_tc_kernel(
    const float* __restrict__ A, int a_nchw,
    const float* __restrict__ W,
    const float* __restrict__ bias,
    float* __restrict__ Cout, int N)
{
    __shared__ float sA[64][SPK];   // [m][k]  (k within current k-tile)
    __shared__ float sB[64][SPK];   // [n][k]

    const int bm = blockIdx.x * 64;
    const int bn = blockIdx.y * 64;
    const int tid  = threadIdx.x;
    const int w    = tid >> 5;
    const int lane = tid & 31;
    const int wm = w >> 2;          // 0..1 -> m0 = wm*32
    const int wn = w & 3;           // 0..3 -> n0 = wn*16
    const int g  = lane >> 2;       // fragment group row 0..7
    const int t4 = lane & 3;        // fragment col 0..3

    float acc[2][2][4];
    #pragma unroll
    for (int mi = 0; mi < 2; mi++)
        #pragma unroll
        for (int ni = 0; ni < 2; ni++)
            #pragma unroll
            for (int u = 0; u < 4; u++) acc[mi][ni][u] = 0.f;

    #pragma unroll
    for (int kt = 0; kt < 2; kt++) {
        if (kt) __syncthreads();
        // ---- stage A k-tile (64m x 64k) ----
        if (a_nchw) {
            const int b = bm >> 12;
            const int sp0 = bm & 4095;
            #pragma unroll
            for (int r = 0; r < 4; r++) {
                int idx = tid + r*256;          // 64k x 16m4
                int k = idx >> 4, m4 = idx & 15;
                float4 v = *(const float4*)&A[(b*CC + kt*64 + k)*4096 + sp0 + m4*4];
                sA[m4*4+0][k] = v.x; sA[m4*4+1][k] = v.y;
                sA[m4*4+2][k] = v.z; sA[m4*4+3][k] = v.w;
            }
        } else {
            #pragma unroll
            for (int r = 0; r < 4; r++) {
                int idx = tid + r*256;          // 64m x 16k4
                int m = idx >> 4, k4 = idx & 15;
                float4 v = ((const float4*)A)[(bm + m)*32 + kt*16 + k4];
                *(float4*)&sA[m][k4*4] = v;
            }
        }
        // ---- stage W k-tile (64n x 64k) ----
        #pragma unroll
        for (int r = 0; r < 4; r++) {
            int idx = tid + r*256;
            int n = idx >> 4, k4 = idx & 15;
            float4 v = ((const float4*)W)[(bn + n)*32 + kt*16 + k4];
            *(float4*)&sB[n][k4*4] = v;
        }
        __syncthreads();

        // ---- 8 k-steps of m16n8k8 ----
        #pragma unroll
        for (int ks = 0; ks < 8; ks++) {
            const int k0 = ks*8;
            unsigned ahi[2][4], alo[2][4];
            #pragma unroll
            for (int mi = 0; mi < 2; mi++) {
                const int m0 = wm*32 + mi*16;
                float f0 = sA[m0 + g    ][k0 + t4    ];
                float f1 = sA[m0 + g + 8][k0 + t4    ];
                float f2 = sA[m0 + g    ][k0 + t4 + 4];
                float f3 = sA[m0 + g + 8][k0 + t4 + 4];
                split_tf32(f0, ahi[mi][0], alo[mi][0]);
                split_tf32(f1, ahi[mi][1], alo[mi][1]);
                split_tf32(f2, ahi[mi][2], alo[mi][2]);
                split_tf32(f3, ahi[mi][3], alo[mi][3]);
            }
            unsigned bhi[2][2], blo[2][2];
            #pragma unroll
            for (int ni = 0; ni < 2; ni++) {
                const int n0 = wn*16 + ni*8;
                float f0 = sB[n0 + g][k0 + t4    ];
                float f1 = sB[n0 + g][k0 + t4 + 4];
                split_tf32(f0, bhi[ni][0], blo[ni][0]);
                split_tf32(f1, bhi[ni][1], blo[ni][1]);
            }
            #pragma unroll
            for (int mi = 0; mi < 2; mi++)
                #pragma unroll
                for (int ni = 0; ni < 2; ni++) {
                    mma8(acc[mi][ni], ahi[mi], bhi[ni]);
                    mma8(acc[mi][ni], ahi[mi], blo[ni]);
                    mma8(acc[mi][ni], alo[mi], bhi[ni]);
                }
        }
    }

    // ---- epilogue: fragment rows g/g+8, cols t4*2, t4*2+1 ----
    #pragma unroll
    for (int mi = 0; mi < 2; mi++) {
        #pragma unroll
        for (int ni = 0; ni < 2; ni++) {
            const int row0 = bm + wm*32 + mi*16 + g;
            const int col  = bn + wn*16 + ni*8 + t4*2;
            float b0 = bias[col], b1 = bias[col + 1];
            float2 v0 = make_float2(acc[mi][ni][0] + b0, acc[mi][ni][1] + b1);
            float2 v1 = make_float2(acc[mi][ni][2] + b0, acc[mi][ni][3] + b1);
            *(float2*)&Cout[row0*N + col]       = v0;
            *(float2*)&Cout[(row0 + 8)*N + col] = v1;
        }
    }
}

// ----------------------------------------------------------------------------
// Attention v3 (known good): 2x2 pixel tile, 128 thr, warp = head.
// ----------------------------------------------------------------------------
#define KP 132
#define ATTN_SMEM ((64*KP*2 + 4*KP + 4*52) * 4)   // 70528 bytes

__global__ void __launch_bounds__(128) attn3_kernel(
    const float* __restrict__ qkv,
    const float* __restrict__ rpb,   // [NH][13][13]
    float* __restrict__ out)
{
    extern __shared__ float dsm[];
    float* sK = dsm;              // [64][KP]
    float* sV = sK + 64*KP;       // [64][KP]
    float* sq = sV + 64*KP;       // [4][KP]
    float* sc = sq + 4*KP;        // [4 heads][52]

    const int blk = blockIdx.x;          // 2048 = 2 * 32 * 32
    const int b  = blk >> 10;
    const int ti = (blk >> 5) & 31;
    const int tj = blk & 31;
    const int i0 = ti*2, j0 = tj*2;
    const int r0 = min(max(i0 - 3, 0), HH - 8);
    const int c0 = min(max(j0 - 3, 0), WW - 8);
    const int tid = threadIdx.x;
    const int h = tid >> 5;
    const int lane = tid & 31;

    #pragma unroll
    for (int it = 0; it < 32; it++) {
        int idx = tid + it*128;
        int row = idx >> 6, c4 = idx & 63;
        int wr = row >> 3, wc = row & 7;
        int tt = (b*HH + r0 + wr)*WW + c0 + wc;
        float4 v = ((const float4*)qkv)[tt*96 + 32 + c4];
        if (c4 < 32) *(float4*)&sK[row*KP + c4*4] = v;
        else         *(float4*)&sV[row*KP + (c4-32)*4] = v;
    }
    {
        int p = tid >> 5, c4 = tid & 31;
        int tt = (b*HH + i0 + (p >> 1))*WW + j0 + (p & 1);
        float4 v = ((const float4*)qkv)[tt*96 + c4];
        const float s = 0.17677669529663687f;   // 32^-0.5
        v.x *= s; v.y *= s; v.z *= s; v.w *= s;
        *(float4*)&sq[p*KP + c4*4] = v;
    }
    __syncthreads();

    const float* rp = rpb + h*169;

    #pragma unroll
    for (int p = 0; p < 4; p++) {
        const int i = i0 + (p >> 1), j = j0 + (p & 1);
        const int si = min(max(i - 3, 0), HH - KS);
        const int sj = min(max(j - 3, 0), WW - KS);
        const int wr0 = si - r0, wc0 = sj - c0;
        const int bi0 = 6 - (i - si), bj0 = 6 - (j - sj);

        float4 q[8];
        const float4* qp = (const float4*)(sq + p*KP + h*DH);
        #pragma unroll
        for (int u = 0; u < 8; u++) q[u] = qp[u];

        float s0, s1;
        {
            int n = lane;
            int np = n/7, nq = n - np*7;
            const float4* kp = (const float4*)(sK + ((wr0+np)*8 + wc0+nq)*KP + h*DH);
            float ax=0.f, ay=0.f, az=0.f, aw=0.f;
            #pragma unroll
            for (int u = 0; u < 8; u++) {
                float4 kv = kp[u];
                ax += q[u].x*kv.x; ay += q[u].y*kv.y;
                az += q[u].z*kv.z; aw += q[u].w*kv.w;
            }
            s0 = (ax+ay) + (az+aw) + rp[(np+bi0)*13 + nq+bj0];
        }
        const int n2 = lane + 32;
        if (n2 < KK) {
            int np = n2/7, nq = n2 - np*7;
            const float4* kp = (const float4*)(sK + ((wr0+np)*8 + wc0+nq)*KP + h*DH);
            float ax=0.f, ay=0.f, az=0.f, aw=0.f;
            #pragma unroll
            for (int u = 0; u < 8; u++) {
                float4 kv = kp[u];
                ax += q[u].x*kv.x; ay += q[u].y*kv.y;
                az += q[u].z*kv.z; aw += q[u].w*kv.w;
            }
            s1 = (ax+ay) + (az+aw) + rp[(np+bi0)*13 + nq+bj0];
        } else s1 = -1e30f;

        float m = fmaxf(s0, s1);
        #pragma unroll
        for (int o = 16; o > 0; o >>= 1) m = fmaxf(m, __shfl_xor_sync(0xffffffffu, m, o));
        float e0 = __expf(s0 - m);
        float e1 = (n2 < KK) ? __expf(s1 - m) : 0.f;
        float sum = e0 + e1;
        #pragma unroll
        for (int o = 16; o > 0; o >>= 1) sum += __shfl_xor_sync(0xffffffffu, sum, o);
        const float inv = 1.f / sum;

        __syncwarp();
        sc[h*52 + lane] = e0 * inv;
        if (n2 < KK) sc[h*52 + n2] = e1 * inv;
        __syncwarp();

        float oa = 0.f, ob = 0.f;
        #pragma unroll
        for (int np = 0; np < 7; np++) {
            const float* vrow = sV + ((wr0+np)*8 + wc0)*KP + h*DH + lane;
            const float* prow = sc + h*52 + np*7;
            oa += prow[0]*vrow[0*KP] + prow[2]*vrow[2*KP]
                + prow[4]*vrow[4*KP] + prow[6]*vrow[6*KP];
            ob += prow[1]*vrow[1*KP] + prow[3]*vrow[3*KP]
                + prow[5]*vrow[5*KP];
        }
        int tt = (b*HH + i)*WW + j;
        out[(size_t)tt*CC + h*DH + lane] = oa + ob;
        __syncwarp();
    }
}

// ----------------------------------------------------------------------------
// Final LayerNorm over C + NHWC -> NCHW transpose.
// ----------------------------------------------------------------------------
__global__ void ln_kernel(const float* __restrict__ y,
                          const float* __restrict__ g,
                          const float* __restrict__ bta,
                          float* __restrict__ out)
{
    __shared__ float s[64][133];
    __shared__ float mu[64], rs[64];

    const int row = blockIdx.x;
    const int b = row >> 6, i = row & 63;
    const int base = row * 64 * CC;
    const int tid = threadIdx.x;

    for (int idx = tid; idx < 64*CC; idx += 256) {
        int jj = idx >> 7, c = idx & 127;
        s[jj][c] = y[base + idx];
    }
    __syncthreads();

    if (tid < 64) {
        float sum = 0.f, sq = 0.f;
        #pragma unroll 8
        for (int c = 0; c < CC; c++) {
            float v = s[tid][c];
            sum += v; sq += v*v;
        }
        float m = sum * (1.f/CC);
        mu[tid] = m;
        rs[tid] = rsqrtf(sq * (1.f/CC) - m*m + 1e-5f);
    }
    __syncthreads();

    for (int idx = tid; idx < 64*CC; idx += 256) {
        int c = idx >> 6, jj = idx & 63;
        float v = (s[jj][c] - mu[jj]) * rs[jj] * g[c] + bta[c];
        out[((b*CC + c)*HH + i)*WW + jj] = v;
    }
}

// ----------------------------------------------------------------------------
extern "C" void kernel_launch(void* const* d_in, const int* in_sizes, int n_in,
                              void* d_out, int out_size)
{
    const float* x      = (const float*)d_in[0];
    const float* qkv_w  = (const float*)d_in[1];
    const float* qkv_b  = (const float*)d_in[2];
    const float* rpb    = (const float*)d_in[3];
    const float* proj_w = (const float*)d_in[4];
    const float* proj_b = (const float*)d_in[5];
    const float* ln_g   = (const float*)d_in[6];
    const float* ln_b   = (const float*)d_in[7];
    float* outp = (float*)d_out;

    float *qkvbuf, *attbuf, *y1, *y2;
    cudaGetSymbolAddress((void**)&qkvbuf, g_qkv);
    cudaGetSymbolAddress((void**)&attbuf, g_att);
    cudaGetSymbolAddress((void**)&y1, g_y1);
    cudaGetSymbolAddress((void**)&y2, g_y2);

    static int smem_set = 0;
    if (!smem_set) {
        cudaFuncSetAttribute(attn3_kernel,
                             cudaFuncAttributeMaxDynamicSharedMemorySize,
                             ATTN_SMEM);
        smem_set = 1;
    }

    dim3 gq(NTOK/64, (3*CC)/64);   // 128 x 6
    dim3 gp(NTOK/64, CC/64);       // 128 x 2
    const int RPB_L = NH*13*13;
    const int NATB = BB*32*32;     // 2048

    // ---- layer 0 ----
    sgemm_tc_kernel<<<gq, 256>>>(x, 1, qkv_w, qkv_b, qkvbuf, 3*CC);
    attn3_kernel<<<NATB, 128, ATTN_SMEM>>>(qkvbuf, rpb, attbuf);
    sgemm_tc_kernel<<<gp, 256>>>(attbuf, 0, proj_w, proj_b, y1, CC);

    // ---- layer 1 ----
    sgemm_tc_kernel<<<gq, 256>>>(y1, 0, qkv_w + 3*CC*CC, qkv_b + 3*CC, qkvbuf, 3*CC);
    attn3_kernel<<<NATB, 128, ATTN_SMEM>>>(qkvbuf, rpb + RPB_L, attbuf);
    sgemm_tc_kernel<<<gp, 256>>>(attbuf, 0, proj_w + CC*CC, proj_b + CC, y2, CC);

    // ---- LN + transpose ----
    ln_kernel<<<BB*HH, 256>>>(y2, ln_g, ln_b, outp);
}